// round 15
// baseline (speedup 1.0000x reference)
#include <cuda_runtime.h>
#include <cuda_fp16.h>
#include <cstdint>
#include <math.h>

#define Bsz 32
#define Nn  1024
#define Dd  128
#define NROWS (Bsz*Nn)

// Scratch (device globals: allocation-free rule). u32 = fp16x2 pairs.
__device__ float    g_qa[NROWS];             // qa[j] = P[j].wa
__device__ uint32_t g_Qh[NROWS * 64];        // (P*wc) fp16 (flash Q plane)
__device__ uint32_t g_Ph[NROWS * 64];        // P fp16      (flash K/V plane)
// X = [P | itr] as fp16 k16 A-fragments:
// ((rb*16 + kb)*32 + lane)*4 : a0..a3
__device__ uint32_t g_Xf16[(NROWS / 16) * 16 * 32 * 4];
// W as fp16 k16 B-fragments: (((g*16+kb)*16+nb)*32+lane)*2 : {b0, b1}
__device__ uint32_t g_Wf16[3 * 16 * 16 * 32 * 2];

// ===========================================================================
// helpers
// ===========================================================================
__device__ __forceinline__ uint32_t smem_u32(const void* p) {
    uint32_t a;
    asm("{ .reg .u64 t; cvta.to.shared.u64 t, %1; cvt.u32.u64 %0, t; }" : "=r"(a) : "l"(p));
    return a;
}
__device__ __forceinline__ void ldsm_x4(uint32_t a[4], uint32_t addr) {
    asm volatile("ldmatrix.sync.aligned.m8n8.x4.shared.b16 {%0,%1,%2,%3}, [%4];"
        : "=r"(a[0]), "=r"(a[1]), "=r"(a[2]), "=r"(a[3]) : "r"(addr));
}
__device__ __forceinline__ void ldsm_x4t(uint32_t a[4], uint32_t addr) {
    asm volatile("ldmatrix.sync.aligned.m8n8.x4.trans.shared.b16 {%0,%1,%2,%3}, [%4];"
        : "=r"(a[0]), "=r"(a[1]), "=r"(a[2]), "=r"(a[3]) : "r"(addr));
}
__device__ __forceinline__ void mma_f16(float c[4], const uint32_t a[4], const uint32_t b[2]) {
    asm volatile("mma.sync.aligned.m16n8k16.row.col.f32.f16.f16.f32 "
        "{%0,%1,%2,%3}, {%4,%5,%6,%7}, {%8,%9}, {%0,%1,%2,%3};"
        : "+f"(c[0]), "+f"(c[1]), "+f"(c[2]), "+f"(c[3])
        : "r"(a[0]), "r"(a[1]), "r"(a[2]), "r"(a[3]), "r"(b[0]), "r"(b[1]));
}
// pack (hi, lo) floats -> fp16x2 (first src -> HIGH half)
__device__ __forceinline__ uint32_t cvt2h(float hi, float lo) {
    uint32_t d;
    asm("cvt.rn.f16x2.f32 %0, %1, %2;" : "=r"(d) : "f"(hi), "f"(lo));
    return d;
}
__device__ __forceinline__ void cpa16(uint32_t dst, const void* src) {
    asm volatile("cp.async.cg.shared.global [%0], [%1], 16;" :: "r"(dst), "l"(src));
}
#define CP_COMMIT()  asm volatile("cp.async.commit_group;" ::: "memory")
#define CP_WAIT0()   asm volatile("cp.async.wait_group 0;" ::: "memory")

// ===========================================================================
// fused prep kernel: blocks [0,96) = W fragments; [96, 96+4096) = qa + planes;
// [96+4096, 96+4096+2048) = X P-half fragments. All 256-thread blocks.
// ===========================================================================
#define PREP_W  96
#define PREP_P  4096
#define PREP_X  2048

__global__ void prep_all(const float* __restrict__ P, const float* __restrict__ w,
                         const float* __restrict__ w1, const float* __restrict__ w2,
                         const float* __restrict__ w3) {
    const int bid = blockIdx.x;
    if (bid < PREP_W) {
        // ---- W fp16 B-fragments: idx = ((g*16+kb)*16+nb)*32+lane ----
        int idx = bid * 256 + threadIdx.x;      // 24576 total
        int lane = idx & 31;
        int nb   = (idx >> 5) & 15;
        int kb   = (idx >> 9) & 15;
        int g    = idx >> 13;
        const float* W = (g == 0) ? w1 : (g == 1) ? w2 : w3;
        int k0 = kb * 16 + (lane & 3) * 2;
        int n  = nb * 8 + (lane >> 2);
        uint2 v;
        v.x = cvt2h(W[(k0 + 1) * 128 + n], W[k0 * 128 + n]);
        v.y = cvt2h(W[(k0 + 9) * 128 + n], W[(k0 + 8) * 128 + n]);
        *(uint2*)(g_Wf16 + (size_t)idx * 2) = v;
    } else if (bid < PREP_W + PREP_P) {
        // ---- qa dot + fp16 planes Ph (K/V), Qh (Q = P*wc) ----
        const int row  = (bid - PREP_W) * 8 + (threadIdx.x >> 5);
        const int lane = threadIdx.x & 31;
        const float4 p  = *(const float4*)(P + (size_t)row * Dd + lane * 4);
        const float4 wa = *(const float4*)(w + lane * 4);
        const float4 wc = *(const float4*)(w + 2 * Dd + lane * 4);
        float s = p.x * wa.x + p.y * wa.y + p.z * wa.z + p.w * wa.w;
        #pragma unroll
        for (int off = 16; off > 0; off >>= 1) s += __shfl_xor_sync(0xffffffffu, s, off);
        if (lane == 0) g_qa[row] = s;
        const size_t o = (size_t)row * 64 + lane * 2;
        g_Ph[o]     = cvt2h(p.y, p.x);
        g_Ph[o + 1] = cvt2h(p.w, p.z);
        g_Qh[o]     = cvt2h(p.y * wc.y, p.x * wc.x);
        g_Qh[o + 1] = cvt2h(p.w * wc.w, p.z * wc.z);
    } else {
        // ---- X fp16 A-fragments, P half (kb 0..7); warp = kb ----
        const int rb   = bid - PREP_W - PREP_P;
        const int kb   = threadIdx.x >> 5;
        const int lane = threadIdx.x & 31;
        const int t2 = (lane & 3) * 2, q = lane >> 2;
        const int c0 = kb * 16;
        const float* e0 = P + (size_t)(rb * 16 + q) * Dd;
        const float* e1 = e0 + 8 * Dd;
        uint4 frag;
        frag.x = cvt2h(e0[c0 + t2 + 1],     e0[c0 + t2]);
        frag.y = cvt2h(e1[c0 + t2 + 1],     e1[c0 + t2]);
        frag.z = cvt2h(e0[c0 + 8 + t2 + 1], e0[c0 + 8 + t2]);
        frag.w = cvt2h(e1[c0 + 8 + t2 + 1], e1[c0 + 8 + t2]);
        *(uint4*)(g_Xf16 + (((size_t)rb * 16 + kb) * 32 + lane) * 4) = frag;
    }
}

// ===========================================================================
// fp16 HMMA flash attention (BM=128, BN=128, 256 thr). Unchanged from R14.
// ===========================================================================
#define LDT 136
#define FQH  0
#define FK0  34816
#define FK1  69632
#define FQA0 104448
#define FQA1 104960
#define FTOT 105472

__device__ __forceinline__ void copy_tile(uint32_t dst,
        const uint32_t* __restrict__ src, size_t grow0, int tid) {
    #pragma unroll
    for (int t = 0; t < 8; t++) {
        int idx = tid + t * 256;             // 2048 16B-chunks (128 rows x 16)
        int r = idx >> 4, c8 = idx & 15;
        cpa16(dst + (uint32_t)(r * LDT + c8 * 8) * 2, src + (grow0 + r) * 64 + c8 * 4);
    }
}

__global__ __launch_bounds__(256, 1)
void flash_hmma() {
    extern __shared__ char smem[];
    const uint32_t sb = smem_u32(smem);
    const int tid = threadIdx.x, lane = tid & 31, wm = tid >> 5;
    const int b = blockIdx.y, i0 = blockIdx.x * 128;
    const int lg = lane >> 3, li = lane & 7;
    const int qc2 = (lane & 3) << 1;
    const size_t brow0 = (size_t)b * Nn;

    copy_tile(sb + FQH, g_Qh, brow0 + i0, tid);
    copy_tile(sb + FK0, g_Ph, brow0, tid);
    if (tid < 32) cpa16(sb + FQA0 + tid * 16, g_qa + brow0 + tid * 4);
    CP_COMMIT();
    CP_WAIT0();
    __syncthreads();

    float o[16][4];
    #pragma unroll
    for (int n = 0; n < 16; n++)
        #pragma unroll
        for (int u = 0; u < 4; u++) o[n][u] = 0.f;
    float lsum0 = 0.f, lsum1 = 0.f;

    for (int jt = 0; jt < 8; jt++) {
        const int cur = jt & 1;
        const uint32_t KH = sb + (cur ? FK1 : FK0);
        const float* qas = (const float*)(smem + (cur ? FQA1 : FQA0));

        if (jt < 7) {
            copy_tile(sb + (cur ? FK0 : FK1), g_Ph, brow0 + (jt + 1) * 128, tid);
            if (tid < 32)
                cpa16(sb + (cur ? FQA0 : FQA1) + tid * 16, g_qa + brow0 + (jt + 1) * 128 + tid * 4);
            CP_COMMIT();
        }

        // ---- S = Q @ K^T, k-tile outer ----
        float s[16][4];
        #pragma unroll
        for (int n = 0; n < 16; n++)
            #pragma unroll
            for (int u = 0; u < 4; u++) s[n][u] = 0.f;

        #pragma unroll
        for (int kt = 0; kt < 8; kt++) {
            const int arow = wm * 16 + ((lg & 1) << 3) + li;
            const int acol = kt * 16 + ((lg >> 1) << 3);
            uint32_t ah[4];
            ldsm_x4(ah, sb + FQH + (arow * LDT + acol) * 2);

            const int brw = ((lg >> 1) << 3) + li;
            const int bcl = kt * 16 + ((lg & 1) << 3);
            uint32_t bh[8][4];
            #pragma unroll
            for (int jp = 0; jp < 8; jp++)
                ldsm_x4(bh[jp], KH + ((jp * 16 + brw) * LDT + bcl) * 2);
            #pragma unroll
            for (int jp = 0; jp < 8; jp++) {
                mma_f16(s[2 * jp],     ah, bh[jp]);
                mma_f16(s[2 * jp + 1], ah, bh[jp] + 2);
            }
        }

        // ---- exp (+qa col bias), pack probs as fp16 PV A-fragments ----
        uint32_t ph[8][4];
        #pragma unroll
        for (int jn = 0; jn < 16; jn++) {
            int cb = jn * 8 + qc2;
            float q0 = qas[cb], q1 = qas[cb + 1];
            float p0 = __expf(s[jn][0] + q0);
            float p1 = __expf(s[jn][1] + q1);
            float p2 = __expf(s[jn][2] + q0);
            float p3 = __expf(s[jn][3] + q1);
            lsum0 += p0 + p1;
            lsum1 += p2 + p3;
            int kt = jn >> 1, hv = (jn & 1) << 1;
            ph[kt][hv]     = cvt2h(p1, p0);
            ph[kt][hv + 1] = cvt2h(p3, p2);
        }

        // ---- O += P @ V (V == K tile via trans ldsm) ----
        #pragma unroll
        for (int kt = 0; kt < 8; kt++) {
            const int brw = kt * 16 + ((lg & 1) << 3) + li;
            const int bcl = (lg >> 1) << 3;
            uint32_t bh[8][4];
            #pragma unroll
            for (int dp = 0; dp < 8; dp++)
                ldsm_x4t(bh[dp], KH + (brw * LDT + dp * 16 + bcl) * 2);
            #pragma unroll
            for (int dp = 0; dp < 8; dp++) {
                mma_f16(o[2 * dp],     ph[kt], bh[dp]);
                mma_f16(o[2 * dp + 1], ph[kt], bh[dp] + 2);
            }
        }

        CP_WAIT0();
        __syncthreads();
    }

    // ---- normalize; C-frag pairs ARE fp16 A-frag halves: pack + store ----
    lsum0 += __shfl_xor_sync(0xffffffffu, lsum0, 1);
    lsum0 += __shfl_xor_sync(0xffffffffu, lsum0, 2);
    lsum1 += __shfl_xor_sync(0xffffffffu, lsum1, 1);
    lsum1 += __shfl_xor_sync(0xffffffffu, lsum1, 2);
    const float inv0 = 1.f / lsum0, inv1 = 1.f / lsum1;
    const size_t rbg = (brow0 + i0) / 16 + wm;
    #pragma unroll
    for (int kb = 0; kb < 8; kb++) {
        uint4 frag;
        frag.x = cvt2h(o[2 * kb][1] * inv0,     o[2 * kb][0] * inv0);
        frag.y = cvt2h(o[2 * kb][3] * inv1,     o[2 * kb][2] * inv1);
        frag.z = cvt2h(o[2 * kb + 1][1] * inv0, o[2 * kb + 1][0] * inv0);
        frag.w = cvt2h(o[2 * kb + 1][3] * inv1, o[2 * kb + 1][2] * inv1);
        *(uint4*)(g_Xf16 + ((rbg * 16 + 8 + kb) * 32 + lane) * 4) = frag;
    }
}

// ===========================================================================
// Fragment-direct fused gated MLP, single-pass fp16, occupancy-tuned:
// 8 warps = 2 row-blocks x 4 n-quarters (32 cols each) -> acc 48 regs,
// ~115 regs total, __launch_bounds__(256,2) = 2 CTAs/SM = 16 warps/SM.
// W uint2 fragments triple-buffered (prefetch 2 ahead), A double-buffered.
// ===========================================================================
__global__ __launch_bounds__(256, 2)
void mlp_frag(const float* __restrict__ P,
              const float* __restrict__ b1, const float* __restrict__ b2,
              const float* __restrict__ b3, float* __restrict__ out) {
    const int tid = threadIdx.x, lane = tid & 31, wid = tid >> 5;
    const int rbl = wid & 1, wn = wid >> 1;          // 2 rb x 4 n-quarters
    const int qr = lane >> 2, qc2 = (lane & 3) << 1;
    const size_t rb = (size_t)blockIdx.x * 2 + rbl;

    const uint32_t* wb0 = g_Wf16 + (size_t)wn * 256 + lane * 2; // + g*16384 + kb*1024 + nf*64
    const uint32_t* xb0 = g_Xf16 + (rb * 16 * 32 + lane) * 4;   // + kb*128

    float acc[3][4][4];
    #pragma unroll
    for (int g = 0; g < 3; g++)
        #pragma unroll
        for (int n = 0; n < 4; n++)
            #pragma unroll
            for (int u = 0; u < 4; u++) acc[g][n][u] = 0.f;

    uint2 wv[3][4];
    uint4 av[2];

    // prologue: A(kb=0); W blk0, blk1
    av[0] = *(const uint4*)(xb0);
    #pragma unroll
    for (int nf = 0; nf < 4; nf++)
        wv[0][nf] = *(const uint2*)(wb0 + nf * 64);
    #pragma unroll
    for (int nf = 0; nf < 4; nf++)
        wv[1][nf] = *(const uint2*)(wb0 + 16384 + nf * 64);

    #pragma unroll
    for (int blk = 0; blk < 48; blk++) {
        const int kb = blk / 3, g = blk - 3 * kb;
        if (g == 0 && kb < 15)
            av[(kb + 1) & 1] = *(const uint4*)(xb0 + (kb + 1) * 128);
        if (blk < 46) {
            const int nblk = blk + 2;
            const int nkb = nblk / 3, ng = nblk - 3 * nkb;
            const uint32_t* ws = wb0 + (size_t)ng * 16384 + nkb * 1024;
            #pragma unroll
            for (int nf = 0; nf < 4; nf++)
                wv[nblk % 3][nf] = *(const uint2*)(ws + nf * 64);
        }
        const uint32_t* a = (const uint32_t*)&av[kb & 1];
        const uint2* wc = wv[blk % 3];
        #pragma unroll
        for (int nf = 0; nf < 4; nf++) {
            uint32_t bf[2] = { wc[nf].x, wc[nf].y };
            mma_f16(acc[g][nf], a, bf);
        }
    }

    // ---- epilogue: out = sigmoid(a2+b2)*P + sigmoid(a3+b3)*tanh(a1+b1) ----
    #pragma unroll
    for (int n = 0; n < 4; n++) {
        int c = wn * 32 + n * 8 + qc2;
        float bb1x = b1[c], bb1y = b1[c + 1];
        float bb2x = b2[c], bb2y = b2[c + 1];
        float bb3x = b3[c], bb3y = b3[c + 1];
        #pragma unroll
        for (int half = 0; half < 2; half++) {
            size_t r = rb * 16 + qr + half * 8;
            float2 pv = *(const float2*)(P + r * Dd + c);
            float a1x = acc[0][n][half * 2], a1y = acc[0][n][half * 2 + 1];
            float a2x = acc[1][n][half * 2], a2y = acc[1][n][half * 2 + 1];
            float a3x = acc[2][n][half * 2], a3y = acc[2][n][half * 2 + 1];
            float zx = tanhf(a1x + bb1x), zy = tanhf(a1y + bb1y);
            float rx = 1.f / (1.f + __expf(-(a2x + bb2x)));
            float ry = 1.f / (1.f + __expf(-(a2y + bb2y)));
            float fx = 1.f / (1.f + __expf(-(a3x + bb3x)));
            float fy = 1.f / (1.f + __expf(-(a3y + bb3y)));
            *(float2*)(out + r * Dd + c) =
                make_float2(rx * pv.x + fx * zx, ry * pv.y + fy * zy);
        }
    }
}

// ===========================================================================
extern "C" void kernel_launch(void* const* d_in, const int* in_sizes, int n_in,
                              void* d_out, int out_size) {
    const float* P  = (const float*)d_in[0];
    const float* w  = (const float*)d_in[1];
    const float* w1 = (const float*)d_in[2];
    const float* w2 = (const float*)d_in[3];
    const float* w3 = (const float*)d_in[4];
    const float* b1 = (const float*)d_in[5];
    const float* b2 = (const float*)d_in[6];
    const float* b3 = (const float*)d_in[7];
    float* out = (float*)d_out;

    cudaFuncSetAttribute(flash_hmma, cudaFuncAttributeMaxDynamicSharedMemorySize, FTOT);

    prep_all<<<PREP_W + PREP_P + PREP_X, 256>>>(P, w, w1, w2, w3);

    dim3 fg(Nn / 128, Bsz);
    flash_hmma<<<fg, 256, FTOT>>>();

    mlp_frag<<<NROWS / 32, 256>>>(P, b1, b2, b3, out);
}

// round 16
// speedup vs baseline: 1.3037x; 1.3037x over previous
#include <cuda_runtime.h>
#include <cuda_fp16.h>
#include <cstdint>
#include <math.h>

#define Bsz 32
#define Nn  1024
#define Dd  128
#define NROWS (Bsz*Nn)

// Scratch (device globals: allocation-free rule). u32 = fp16x2 pairs.
__device__ float    g_qa[NROWS];             // qa[j] = P[j].wa
__device__ uint32_t g_Qh[NROWS * 64];        // (P*wc) fp16 (flash Q plane)
__device__ uint32_t g_Ph[NROWS * 64];        // P fp16      (flash K/V plane)
// X = [P | itr] as fp16 k16 A-fragments:
// ((rb*16 + kb)*32 + lane)*4 : a0..a3
__device__ uint32_t g_Xf16[(NROWS / 16) * 16 * 32 * 4];
// W as fp16 k16 B-fragments: (((g*16+kb)*16+nb)*32+lane)*2 : {b0, b1}
__device__ uint32_t g_Wf16[3 * 16 * 16 * 32 * 2];

// ===========================================================================
// helpers
// ===========================================================================
__device__ __forceinline__ uint32_t smem_u32(const void* p) {
    uint32_t a;
    asm("{ .reg .u64 t; cvta.to.shared.u64 t, %1; cvt.u32.u64 %0, t; }" : "=r"(a) : "l"(p));
    return a;
}
__device__ __forceinline__ void ldsm_x4(uint32_t a[4], uint32_t addr) {
    asm volatile("ldmatrix.sync.aligned.m8n8.x4.shared.b16 {%0,%1,%2,%3}, [%4];"
        : "=r"(a[0]), "=r"(a[1]), "=r"(a[2]), "=r"(a[3]) : "r"(addr));
}
__device__ __forceinline__ void ldsm_x4t(uint32_t a[4], uint32_t addr) {
    asm volatile("ldmatrix.sync.aligned.m8n8.x4.trans.shared.b16 {%0,%1,%2,%3}, [%4];"
        : "=r"(a[0]), "=r"(a[1]), "=r"(a[2]), "=r"(a[3]) : "r"(addr));
}
__device__ __forceinline__ void mma_f16(float c[4], const uint32_t a[4], const uint32_t b[2]) {
    asm volatile("mma.sync.aligned.m16n8k16.row.col.f32.f16.f16.f32 "
        "{%0,%1,%2,%3}, {%4,%5,%6,%7}, {%8,%9}, {%0,%1,%2,%3};"
        : "+f"(c[0]), "+f"(c[1]), "+f"(c[2]), "+f"(c[3])
        : "r"(a[0]), "r"(a[1]), "r"(a[2]), "r"(a[3]), "r"(b[0]), "r"(b[1]));
}
// pack (hi, lo) floats -> fp16x2 (first src -> HIGH half)
__device__ __forceinline__ uint32_t cvt2h(float hi, float lo) {
    uint32_t d;
    asm("cvt.rn.f16x2.f32 %0, %1, %2;" : "=r"(d) : "f"(hi), "f"(lo));
    return d;
}
__device__ __forceinline__ void cpa16(uint32_t dst, const void* src) {
    asm volatile("cp.async.cg.shared.global [%0], [%1], 16;" :: "r"(dst), "l"(src));
}
#define CP_COMMIT()  asm volatile("cp.async.commit_group;" ::: "memory")
#define CP_WAIT0()   asm volatile("cp.async.wait_group 0;" ::: "memory")

// ===========================================================================
// prep: per row -> qa dot, fp16 planes Ph (K/V) and Qh (Q = P*wc)
// ===========================================================================
__global__ void prep_kernel(const float* __restrict__ P, const float* __restrict__ w) {
    const int row  = blockIdx.x * 8 + (threadIdx.x >> 5);
    const int lane = threadIdx.x & 31;
    const float4 p  = *(const float4*)(P + (size_t)row * Dd + lane * 4);
    const float4 wa = *(const float4*)(w + lane * 4);
    const float4 wc = *(const float4*)(w + 2 * Dd + lane * 4);
    float s = p.x * wa.x + p.y * wa.y + p.z * wa.z + p.w * wa.w;
    #pragma unroll
    for (int off = 16; off > 0; off >>= 1) s += __shfl_xor_sync(0xffffffffu, s, off);
    if (lane == 0) g_qa[row] = s;
    const size_t o = (size_t)row * 64 + lane * 2;
    g_Ph[o]     = cvt2h(p.y, p.x);
    g_Ph[o + 1] = cvt2h(p.w, p.z);
    g_Qh[o]     = cvt2h(p.y * wc.y, p.x * wc.x);
    g_Qh[o + 1] = cvt2h(p.w * wc.w, p.z * wc.z);
}

// X fp16 A-fragments, P half (kb 0..7). Block = rb, warp = kb.
__global__ void xfrag_p_kernel(const float* __restrict__ P) {
    const int rb   = blockIdx.x;
    const int kb   = threadIdx.x >> 5;
    const int lane = threadIdx.x & 31;
    const int t2 = (lane & 3) * 2, q = lane >> 2;
    const int c0 = kb * 16;
    const float* e0 = P + (size_t)(rb * 16 + q) * Dd;       // row qr
    const float* e1 = e0 + 8 * Dd;                          // row qr+8
    uint4 frag;
    frag.x = cvt2h(e0[c0 + t2 + 1],     e0[c0 + t2]);
    frag.y = cvt2h(e1[c0 + t2 + 1],     e1[c0 + t2]);
    frag.z = cvt2h(e0[c0 + 8 + t2 + 1], e0[c0 + 8 + t2]);
    frag.w = cvt2h(e1[c0 + 8 + t2 + 1], e1[c0 + 8 + t2]);
    *(uint4*)(g_Xf16 + (((size_t)rb * 16 + kb) * 32 + lane) * 4) = frag;
}

// W fp16 B-fragments: idx = ((g*16+kb)*16+nb)*32+lane
__global__ void wsplit_frag(const float* __restrict__ w1, const float* __restrict__ w2,
                            const float* __restrict__ w3) {
    int idx = blockIdx.x * 256 + threadIdx.x;       // 24576 total
    if (idx >= 24576) return;
    int lane = idx & 31;
    int nb   = (idx >> 5) & 15;
    int kb   = (idx >> 9) & 15;
    int g    = idx >> 13;
    const float* W = (g == 0) ? w1 : (g == 1) ? w2 : w3;
    int k0 = kb * 16 + (lane & 3) * 2;
    int n  = nb * 8 + (lane >> 2);
    uint2 v;
    v.x = cvt2h(W[(k0 + 1) * 128 + n], W[k0 * 128 + n]);
    v.y = cvt2h(W[(k0 + 9) * 128 + n], W[(k0 + 8) * 128 + n]);
    *(uint2*)(g_Wf16 + (size_t)idx * 2) = v;
}

// ===========================================================================
// fp16 HMMA flash attention (BM=128, BN=128, 256 thr). Unchanged from R14.
// ===========================================================================
#define LDT 136
#define FQH  0
#define FK0  34816
#define FK1  69632
#define FQA0 104448
#define FQA1 104960
#define FTOT 105472

__device__ __forceinline__ void copy_tile(uint32_t dst,
        const uint32_t* __restrict__ src, size_t grow0, int tid) {
    #pragma unroll
    for (int t = 0; t < 8; t++) {
        int idx = tid + t * 256;             // 2048 16B-chunks (128 rows x 16)
        int r = idx >> 4, c8 = idx & 15;
        cpa16(dst + (uint32_t)(r * LDT + c8 * 8) * 2, src + (grow0 + r) * 64 + c8 * 4);
    }
}

__global__ __launch_bounds__(256, 1)
void flash_hmma() {
    extern __shared__ char smem[];
    const uint32_t sb = smem_u32(smem);
    const int tid = threadIdx.x, lane = tid & 31, wm = tid >> 5;
    const int b = blockIdx.y, i0 = blockIdx.x * 128;
    const int lg = lane >> 3, li = lane & 7;
    const int qc2 = (lane & 3) << 1;
    const size_t brow0 = (size_t)b * Nn;

    copy_tile(sb + FQH, g_Qh, brow0 + i0, tid);
    copy_tile(sb + FK0, g_Ph, brow0, tid);
    if (tid < 32) cpa16(sb + FQA0 + tid * 16, g_qa + brow0 + tid * 4);
    CP_COMMIT();
    CP_WAIT0();
    __syncthreads();

    float o[16][4];
    #pragma unroll
    for (int n = 0; n < 16; n++)
        #pragma unroll
        for (int u = 0; u < 4; u++) o[n][u] = 0.f;
    float lsum0 = 0.f, lsum1 = 0.f;

    for (int jt = 0; jt < 8; jt++) {
        const int cur = jt & 1;
        const uint32_t KH = sb + (cur ? FK1 : FK0);
        const float* qas = (const float*)(smem + (cur ? FQA1 : FQA0));

        if (jt < 7) {
            copy_tile(sb + (cur ? FK0 : FK1), g_Ph, brow0 + (jt + 1) * 128, tid);
            if (tid < 32)
                cpa16(sb + (cur ? FQA0 : FQA1) + tid * 16, g_qa + brow0 + (jt + 1) * 128 + tid * 4);
            CP_COMMIT();
        }

        // ---- S = Q @ K^T, k-tile outer ----
        float s[16][4];
        #pragma unroll
        for (int n = 0; n < 16; n++)
            #pragma unroll
            for (int u = 0; u < 4; u++) s[n][u] = 0.f;

        #pragma unroll
        for (int kt = 0; kt < 8; kt++) {
            const int arow = wm * 16 + ((lg & 1) << 3) + li;
            const int acol = kt * 16 + ((lg >> 1) << 3);
            uint32_t ah[4];
            ldsm_x4(ah, sb + FQH + (arow * LDT + acol) * 2);

            const int brw = ((lg >> 1) << 3) + li;
            const int bcl = kt * 16 + ((lg & 1) << 3);
            uint32_t bh[8][4];
            #pragma unroll
            for (int jp = 0; jp < 8; jp++)
                ldsm_x4(bh[jp], KH + ((jp * 16 + brw) * LDT + bcl) * 2);
            #pragma unroll
            for (int jp = 0; jp < 8; jp++) {
                mma_f16(s[2 * jp],     ah, bh[jp]);
                mma_f16(s[2 * jp + 1], ah, bh[jp] + 2);
            }
        }

        // ---- exp (+qa col bias), pack probs as fp16 PV A-fragments ----
        uint32_t ph[8][4];
        #pragma unroll
        for (int jn = 0; jn < 16; jn++) {
            int cb = jn * 8 + qc2;
            float q0 = qas[cb], q1 = qas[cb + 1];
            float p0 = __expf(s[jn][0] + q0);
            float p1 = __expf(s[jn][1] + q1);
            float p2 = __expf(s[jn][2] + q0);
            float p3 = __expf(s[jn][3] + q1);
            lsum0 += p0 + p1;
            lsum1 += p2 + p3;
            int kt = jn >> 1, hv = (jn & 1) << 1;
            ph[kt][hv]     = cvt2h(p1, p0);
            ph[kt][hv + 1] = cvt2h(p3, p2);
        }

        // ---- O += P @ V (V == K tile via trans ldsm) ----
        #pragma unroll
        for (int kt = 0; kt < 8; kt++) {
            const int brw = kt * 16 + ((lg & 1) << 3) + li;
            const int bcl = (lg >> 1) << 3;
            uint32_t bh[8][4];
            #pragma unroll
            for (int dp = 0; dp < 8; dp++)
                ldsm_x4t(bh[dp], KH + (brw * LDT + dp * 16 + bcl) * 2);
            #pragma unroll
            for (int dp = 0; dp < 8; dp++) {
                mma_f16(o[2 * dp],     ph[kt], bh[dp]);
                mma_f16(o[2 * dp + 1], ph[kt], bh[dp] + 2);
            }
        }

        CP_WAIT0();
        __syncthreads();
    }

    // ---- normalize; C-frag pairs ARE fp16 A-frag halves: pack + store ----
    lsum0 += __shfl_xor_sync(0xffffffffu, lsum0, 1);
    lsum0 += __shfl_xor_sync(0xffffffffu, lsum0, 2);
    lsum1 += __shfl_xor_sync(0xffffffffu, lsum1, 1);
    lsum1 += __shfl_xor_sync(0xffffffffu, lsum1, 2);
    const float inv0 = 1.f / lsum0, inv1 = 1.f / lsum1;
    const size_t rbg = (brow0 + i0) / 16 + wm;
    #pragma unroll
    for (int kb = 0; kb < 8; kb++) {
        uint4 frag;
        frag.x = cvt2h(o[2 * kb][1] * inv0,     o[2 * kb][0] * inv0);
        frag.y = cvt2h(o[2 * kb][3] * inv1,     o[2 * kb][2] * inv1);
        frag.z = cvt2h(o[2 * kb + 1][1] * inv0, o[2 * kb + 1][0] * inv0);
        frag.w = cvt2h(o[2 * kb + 1][3] * inv1, o[2 * kb + 1][2] * inv1);
        *(uint4*)(g_Xf16 + ((rbg * 16 + 8 + kb) * 32 + lane) * 4) = frag;
    }
}

// ===========================================================================
// Fragment-direct fused gated MLP, single-pass fp16 (m16n8k16): no smem,
// no barriers. 8 warps = 4 row-blocks x 2 n-halves (R14 tiling: 64 rows/CTA,
// W L1-reuse by 4 warps). DEEPENED pipeline: W fragments 5-buffer (prefetch
// 4 blocks ahead ~256 cyc), A fragments 4-ring (prefetch 3 kb ahead).
// ===========================================================================
__global__ __launch_bounds__(256, 1)
void mlp_frag(const float* __restrict__ P,
              const float* __restrict__ b1, const float* __restrict__ b2,
              const float* __restrict__ b3, float* __restrict__ out) {
    const int tid = threadIdx.x, lane = tid & 31, wid = tid >> 5;
    const int rbl = wid & 3, wn = wid >> 2;
    const int qr = lane >> 2, qc2 = (lane & 3) << 1;
    const size_t rb = (size_t)blockIdx.x * 4 + rbl;

    const uint32_t* wb0 = g_Wf16 + (size_t)wn * 512 + lane * 2; // + g*16384 + kb*1024 + nf*64
    const uint32_t* xb0 = g_Xf16 + (rb * 16 * 32 + lane) * 4;   // + kb*128

    float acc[3][8][4];
    #pragma unroll
    for (int g = 0; g < 3; g++)
        #pragma unroll
        for (int n = 0; n < 8; n++)
            #pragma unroll
            for (int u = 0; u < 4; u++) acc[g][n][u] = 0.f;

    uint2 wv[5][8];
    uint4 av[4];

    // prologue: A kb 0..2; W blocks 0..3
    av[0] = *(const uint4*)(xb0);
    av[1] = *(const uint4*)(xb0 + 128);
    av[2] = *(const uint4*)(xb0 + 256);
    #pragma unroll
    for (int pb = 0; pb < 4; pb++) {
        const int pkb = pb / 3, pg = pb - 3 * pkb;
        const uint32_t* ws = wb0 + (size_t)pg * 16384 + pkb * 1024;
        #pragma unroll
        for (int nf = 0; nf < 8; nf++)
            wv[pb][nf] = *(const uint2*)(ws + nf * 64);
    }

    #pragma unroll
    for (int blk = 0; blk < 48; blk++) {
        const int kb = blk / 3, g = blk - 3 * kb;
        // prefetch A 3 kb ahead at the start of each kb
        if (g == 0 && kb < 13)
            av[(kb + 3) & 3] = *(const uint4*)(xb0 + (kb + 3) * 128);
        // prefetch W 4 blocks ahead
        if (blk < 44) {
            const int nblk = blk + 4;
            const int nkb = nblk / 3, ng = nblk - 3 * nkb;
            const uint32_t* ws = wb0 + (size_t)ng * 16384 + nkb * 1024;
            #pragma unroll
            for (int nf = 0; nf < 8; nf++)
                wv[nblk % 5][nf] = *(const uint2*)(ws + nf * 64);
        }
        const uint32_t* a = (const uint32_t*)&av[kb & 3];
        const uint2* wc = wv[blk % 5];
        #pragma unroll
        for (int nf = 0; nf < 8; nf++) {
            uint32_t bf[2] = { wc[nf].x, wc[nf].y };
            mma_f16(acc[g][nf], a, bf);
        }
    }

    // ---- epilogue: out = sigmoid(a2+b2)*P + sigmoid(a3+b3)*tanh(a1+b1) ----
    #pragma unroll
    for (int n = 0; n < 8; n++) {
        int c = wn * 64 + n * 8 + qc2;
        float bb1x = b1[c], bb1y = b1[c + 1];
        float bb2x = b2[c], bb2y = b2[c + 1];
        float bb3x = b3[c], bb3y = b3[c + 1];
        #pragma unroll
        for (int half = 0; half < 2; half++) {
            size_t r = rb * 16 + qr + half * 8;
            float2 pv = *(const float2*)(P + r * Dd + c);
            float a1x = acc[0][n][half * 2], a1y = acc[0][n][half * 2 + 1];
            float a2x = acc[1][n][half * 2], a2y = acc[1][n][half * 2 + 1];
            float a3x = acc[2][n][half * 2], a3y = acc[2][n][half * 2 + 1];
            float zx = tanhf(a1x + bb1x), zy = tanhf(a1y + bb1y);
            float rx = 1.f / (1.f + __expf(-(a2x + bb2x)));
            float ry = 1.f / (1.f + __expf(-(a2y + bb2y)));
            float fx = 1.f / (1.f + __expf(-(a3x + bb3x)));
            float fy = 1.f / (1.f + __expf(-(a3y + bb3y)));
            *(float2*)(out + r * Dd + c) =
                make_float2(rx * pv.x + fx * zx, ry * pv.y + fy * zy);
        }
    }
}

// ===========================================================================
extern "C" void kernel_launch(void* const* d_in, const int* in_sizes, int n_in,
                              void* d_out, int out_size) {
    const float* P  = (const float*)d_in[0];
    const float* w  = (const float*)d_in[1];
    const float* w1 = (const float*)d_in[2];
    const float* w2 = (const float*)d_in[3];
    const float* w3 = (const float*)d_in[4];
    const float* b1 = (const float*)d_in[5];
    const float* b2 = (const float*)d_in[6];
    const float* b3 = (const float*)d_in[7];
    float* out = (float*)d_out;

    cudaFuncSetAttribute(flash_hmma, cudaFuncAttributeMaxDynamicSharedMemorySize, FTOT);

    wsplit_frag<<<96, 256>>>(w1, w2, w3);
    prep_kernel<<<NROWS / 8, 256>>>(P, w);
    xfrag_p_kernel<<<NROWS / 16, 256>>>(P);

    dim3 fg(Nn / 128, Bsz);
    flash_hmma<<<fg, 256, FTOT>>>();

    mlp_frag<<<NROWS / 64, 256>>>(P, b1, b2, b3, out);
}